// round 9
// baseline (speedup 1.0000x reference)
#include <cuda_runtime.h>
#include <cuda_fp16.h>
#include <cstdint>

// Problem constants
#define NTOK 2048          // B*T
#define DDIM 1024
#define EXP  16
#define FF   512
#define FSH  2048
#define PAIRS (NTOK*2)

// ---------------- scratch (device globals) ----------------------------------
__device__ float g_probs[NTOK * EXP];
__device__ float g_topkw[PAIRS];
__device__ int   g_topki[PAIRS];
__device__ float g_sgate[NTOK];
__device__ int   g_count[EXP];
__device__ int   g_offset[EXP];
__device__ int   g_perm[PAIRS];
__device__ float g_y   [(size_t)PAIRS * DDIM];   // weighted expert outputs
__device__ float g_shf [(size_t)NTOK * DDIM];    // shared output (f32)

// fp16 packed as u32 (2 per u32), row-major [rows][K/2] u32
__device__ uint32_t g_xh [NTOK * 512];          // x       [T][D]
__device__ uint32_t g_wg [EXP * 1024 * 512];    // gup     [E*2F][D]
__device__ uint32_t g_wd [EXP * 1024 * 256];    // down    [E*D][F]
__device__ uint32_t g_g1 [FSH * 512];           // sh gate [FS][D]
__device__ uint32_t g_u1 [FSH * 512];           // sh up   [FS][D]
__device__ uint32_t g_d1 [DDIM * 1024];         // sh down [D][FS]
__device__ uint32_t g_eh [PAIRS * 256];         // exp hid [P][F]
__device__ uint32_t g_sh2[NTOK * 1024];         // sh hid  [T][FS]

// ---------------- asm helpers ------------------------------------------------
__device__ __forceinline__ uint32_t smem_u32(const void* p) {
    uint32_t a;
    asm("{ .reg .u64 t; cvta.to.shared.u64 t, %1; cvt.u32.u64 %0, t; }" : "=r"(a) : "l"(p));
    return a;
}
#define CPA(d, s) asm volatile("cp.async.cg.shared.global [%0], [%1], 16;" :: "r"(d), "l"(s) : "memory")
#define CPC()     asm volatile("cp.async.commit_group;" ::: "memory")
#define CPW2()    asm volatile("cp.async.wait_group 2;" ::: "memory")
#define CPW1()    asm volatile("cp.async.wait_group 1;" ::: "memory")
#define CPW0()    asm volatile("cp.async.wait_group 0;" ::: "memory")
#define LDSM4(r, a) \
    asm volatile("ldmatrix.sync.aligned.m8n8.x4.shared.b16 {%0,%1,%2,%3}, [%4];" \
        : "=r"((r)[0]), "=r"((r)[1]), "=r"((r)[2]), "=r"((r)[3]) : "r"(a))
#define MMA16(d, a, b0, b1) \
    asm volatile("mma.sync.aligned.m16n8k16.row.col.f32.f16.f16.f32 " \
        "{%0,%1,%2,%3},{%4,%5,%6,%7},{%8,%9},{%0,%1,%2,%3};" \
        : "+f"((d)[0]), "+f"((d)[1]), "+f"((d)[2]), "+f"((d)[3]) \
        : "r"((a)[0]), "r"((a)[1]), "r"((a)[2]), "r"((a)[3]), "r"(b0), "r"(b1))

// ---------------- mega convert kernel (launch #1) ----------------------------
// straight cvt blocks: x, gup, dwn; then transpose-cvt blocks for shg/shu/shd.
#define CVT_N1 (NTOK * DDIM / 4)
#define CVT_N2 (EXP * 1024 * 1024 / 4)
#define CVT_N3 (EXP * 1024 * 512 / 4)
#define NB_STRAIGHT ((CVT_N1 + CVT_N2 + CVT_N3) / 256)   // 26624
#define NB_T_EACH   2048
#define NB_CVT (NB_STRAIGHT + 3 * NB_T_EACH)             // 32768

__global__ void k_cvt_mega(const float* __restrict__ x, const float* __restrict__ gup,
                           const float* __restrict__ dwn, const float* __restrict__ shg,
                           const float* __restrict__ shu, const float* __restrict__ shd) {
    int bx = blockIdx.x;
    int tid = threadIdx.x;
    if (bx < NB_STRAIGHT) {
        int i = bx * 256 + tid;
        const float* in; uint32_t* oh; int idx;
        if (i < CVT_N1)                { in = x;   oh = g_xh; idx = i; }
        else if (i < CVT_N1 + CVT_N2)  { in = gup; oh = g_wg; idx = i - CVT_N1; }
        else                           { in = dwn; oh = g_wd; idx = i - CVT_N1 - CVT_N2; }
        float4 v = ((const float4*)in)[idx];
        __half2 a = __floats2half2_rn(v.x, v.y);
        __half2 b = __floats2half2_rn(v.z, v.w);
        ((uint2*)oh)[idx] = make_uint2(*reinterpret_cast<uint32_t*>(&a),
                                       *reinterpret_cast<uint32_t*>(&b));
        return;
    }
    // transpose-convert: in [Kdim][Ndim] f32 -> out [Ndim][Kdim/2] u32
    int tb = bx - NB_STRAIGHT;
    int z = tb / NB_T_EACH, r = tb % NB_T_EACH;
    const float* in; uint32_t* oh; int Kdim, Ndim, k0, n0;
    if (z == 0)      { in = shg; oh = g_g1; Kdim = DDIM; Ndim = FSH; }
    else if (z == 1) { in = shu; oh = g_u1; Kdim = DDIM; Ndim = FSH; }
    else             { in = shd; oh = g_d1; Kdim = FSH; Ndim = DDIM; }
    if (z < 2) { n0 = (r & 63) * 32; k0 = (r >> 6) * 32; }
    else       { n0 = (r & 31) * 32; k0 = (r >> 5) * 32; }
    __shared__ float tile[32][33];
    int tx = tid & 31, ty = tid >> 5;   // 32 x 8
#pragma unroll
    for (int i = 0; i < 4; i++)
        tile[ty + i * 8][tx] = in[(size_t)(k0 + ty + i * 8) * Ndim + n0 + tx];
    __syncthreads();
    int nl = tid >> 3, q = tid & 7;
    size_t orow = (size_t)(n0 + nl) * (Kdim / 2) + (k0 >> 1);
#pragma unroll
    for (int j = 0; j < 2; j++) {
        int idx = q * 2 + j, kl = idx * 2;
        __half2 h = __floats2half2_rn(tile[kl][nl], tile[kl + 1][nl]);
        oh[orow + idx] = *reinterpret_cast<uint32_t*>(&h);
    }
}

// ---------------- router (launch #2) -----------------------------------------
__global__ void k_router(const float* __restrict__ x, const float* __restrict__ rw,
                         const float* __restrict__ sgw) {
    int t = blockIdx.x * 4 + (threadIdx.x >> 5);
    int lane = threadIdx.x & 31;
    if (t >= NTOK) return;
    const float* xr = x + (size_t)t * DDIM;
    float acc[EXP];
#pragma unroll
    for (int e = 0; e < EXP; e++) acc[e] = 0.f;
    float sg = 0.f;
    for (int j = lane; j < DDIM; j += 32) {
        float xv = xr[j];
        const float* r = rw + (size_t)j * EXP;
#pragma unroll
        for (int e = 0; e < EXP; e++) acc[e] = fmaf(xv, r[e], acc[e]);
        sg = fmaf(xv, sgw[j], sg);
    }
#pragma unroll
    for (int off = 16; off; off >>= 1) {
#pragma unroll
        for (int e = 0; e < EXP; e++) acc[e] += __shfl_xor_sync(0xffffffffu, acc[e], off);
        sg += __shfl_xor_sync(0xffffffffu, sg, off);
    }
    float mx = acc[0];
#pragma unroll
    for (int e = 1; e < EXP; e++) mx = fmaxf(mx, acc[e]);
    float pr[EXP]; float sum = 0.f;
#pragma unroll
    for (int e = 0; e < EXP; e++) { pr[e] = __expf(acc[e] - mx); sum += pr[e]; }
    float inv = 1.f / sum;
#pragma unroll
    for (int e = 0; e < EXP; e++) pr[e] *= inv;
    if (lane < EXP) g_probs[(size_t)t * EXP + lane] = pr[lane];
    if (lane == 0) {
        int i1 = 0; float p1 = pr[0];
#pragma unroll
        for (int e = 1; e < EXP; e++) if (pr[e] > p1) { p1 = pr[e]; i1 = e; }
        int i2 = (i1 == 0) ? 1 : 0; float p2 = pr[i2];
#pragma unroll
        for (int e = 0; e < EXP; e++) if (e != i1 && pr[e] > p2) { p2 = pr[e]; i2 = e; }
        float s2 = p1 + p2; if (s2 < 1e-9f) s2 = 1e-9f;
        g_topkw[t * 2 + 0] = p1 / s2;  g_topkw[t * 2 + 1] = p2 / s2;
        g_topki[t * 2 + 0] = i1;       g_topki[t * 2 + 1] = i2;
        g_sgate[t] = 1.f / (1.f + __expf(-sg));
    }
}

// ---------------- deterministic scan+scatter (launch #3, 1 block) ------------
__global__ void k_scansc() {
    __shared__ int hist[256][EXP];
    __shared__ int s_cnt[EXP], s_off[EXP];
    int tid = threadIdx.x;
    int lo = tid * 16;
    int h[EXP];
#pragma unroll
    for (int e = 0; e < EXP; e++) h[e] = 0;
    int el[16];
#pragma unroll
    for (int j = 0; j < 16; j++) { el[j] = g_topki[lo + j]; h[el[j]]++; }
#pragma unroll
    for (int e = 0; e < EXP; e++) hist[tid][e] = h[e];
    __syncthreads();
    if (tid < EXP) {
        int run = 0;
        for (int t = 0; t < 256; t++) { int v = hist[t][tid]; hist[t][tid] = run; run += v; }
        s_cnt[tid] = run;
    }
    __syncthreads();
    if (tid == 0) {
        int s = 0;
        for (int e = 0; e < EXP; e++) {
            s_off[e] = s; g_offset[e] = s; g_count[e] = s_cnt[e]; s += s_cnt[e];
        }
    }
    __syncthreads();
    int run[EXP];
#pragma unroll
    for (int e = 0; e < EXP; e++) run[e] = s_off[e] + hist[tid][e];
#pragma unroll
    for (int j = 0; j < 16; j++) {
        int e = el[j];
        g_perm[run[e]++] = lo + j;
    }
}

// ---------------- HMMA GEMM core: 128x256 tile, BK=64, single fp16 ----------
#define ROWB   144              // bytes per smem row (64 halfs + 8 pad)
#define A_BYTES (128 * ROWB)    // 18432
#define B_BYTES (256 * ROWB)    // 36864
#define STAGE  (A_BYTES + B_BYTES)  // 55296
#define NSTG   4
#define SMBYTES (NSTG * STAGE)  // 221184

__device__ __forceinline__ void g_load(uint32_t sb, int s, int c, int lr, int lc, int br,
                                       const uint32_t* aRow, const uint32_t* bRow) {
    uint32_t stg = sb + s * STAGE;
    uint32_t ad = stg + lr * ROWB + lc * 64;
    const uint32_t* as = aRow + c * 32 + lc * 16;
#pragma unroll
    for (int i = 0; i < 4; i++) CPA(ad + i * 16, as + i * 4);
    uint32_t bd = stg + A_BYTES + br * ROWB;
    const uint32_t* bs = bRow + c * 32;
#pragma unroll
    for (int i = 0; i < 8; i++) CPA(bd + i * 16, bs + i * 4);
}

__device__ __forceinline__ void g_mainloop(float acc[2][16][4], uint32_t sb, int NC,
                                           int lr, int lc, int br, int wr, int wc, int lane,
                                           const uint32_t* aRow, const uint32_t* bRow) {
    g_load(sb, 0, 0, lr, lc, br, aRow, bRow); CPC();
    if (NC > 1) { g_load(sb, 1, 1, lr, lc, br, aRow, bRow); CPC(); }
    if (NC > 2) { g_load(sb, 2, 2, lr, lc, br, aRow, bRow); CPC(); }
    for (int c = 0; c < NC; c++) {
        int rem = NC - c;
        if (rem >= 3) CPW2(); else if (rem == 2) CPW1(); else CPW0();
        __syncthreads();
        if (c + 3 < NC) { g_load(sb, (c + 3) & 3, c + 3, lr, lc, br, aRow, bRow); CPC(); }
        uint32_t stg = sb + (c & 3) * STAGE;
#pragma unroll
        for (int ks = 0; ks < 4; ks++) {
            int ko = ks * 32;
            uint32_t ah[2][4];
#pragma unroll
            for (int mt = 0; mt < 2; mt++) {
                uint32_t ad = stg + (wr + mt * 16 + (lane & 15)) * ROWB + ko + (lane >> 4) * 16;
                LDSM4(ah[mt], ad);
            }
            uint32_t bh[8][4];
#pragma unroll
            for (int p = 0; p < 8; p++) {
                uint32_t bd = stg + A_BYTES + (wc + p * 16 + (lane & 15)) * ROWB + ko + (lane >> 4) * 16;
                LDSM4(bh[p], bd);
            }
#pragma unroll
            for (int mt = 0; mt < 2; mt++)
#pragma unroll
                for (int p = 0; p < 8; p++) {
                    MMA16(acc[mt][2 * p],     ah[mt], bh[p][0], bh[p][2]);
                    MMA16(acc[mt][2 * p + 1], ah[mt], bh[p][1], bh[p][3]);
                }
        }
    }
    __syncthreads();   // smem reused by epilogue
}

// ---- up GEMM (launch #4): x @ {gate,up}^T fused silu*up -> fp16 hidden -----
__global__ void __launch_bounds__(256, 1) k_up() {
    extern __shared__ char sm[];
    const int tid = threadIdx.x;
    const int lr = tid >> 1, lc = tid & 1, br = tid;
    const int w = tid >> 5, lane = tid & 31;
    const int wn = w & 1, wm = w >> 1;
    const int wr2 = wm * 32, wc2 = wn * 128;

    int bx = blockIdx.x;
    bool shmode; int e = 0, m0, f0, cnt = 0, basep = 0;
    if (bx < 256) {
        shmode = true;
        m0 = (bx >> 4) * 128; f0 = (bx & 15) * 128;
    } else {
        shmode = false;
        bx -= 256;
        e = bx >> 7; int rem = bx & 127;
        m0 = (rem >> 2) * 128; f0 = (rem & 3) * 128;
        cnt = g_count[e]; basep = g_offset[e];
        if (m0 >= cnt) return;
    }

    const uint32_t *aRow, *bRow;
    if (shmode) {
        aRow = g_xh + (size_t)(m0 + lr) * 512;
        bRow = (br < 128) ? g_g1 + (size_t)(f0 + br) * 512
                          : g_u1 + (size_t)(f0 + br - 128) * 512;
    } else {
        int rr = m0 + lr; if (rr >= cnt) rr = cnt - 1;
        int token = g_perm[basep + rr] >> 1;
        aRow = g_xh + (size_t)token * 512;
        int brow = (br < 128) ? (e * 1024 + f0 + br) : (e * 1024 + 512 + f0 + br - 128);
        bRow = g_wg + (size_t)brow * 512;
    }

    const uint32_t sb = smem_u32(sm);
    float acc[2][16][4];
#pragma unroll
    for (int a = 0; a < 2; a++)
#pragma unroll
        for (int b = 0; b < 16; b++)
#pragma unroll
            for (int c = 0; c < 4; c++) acc[a][b][c] = 0.f;

    g_mainloop(acc, sb, 16, lr, lc, br, wr2, wc2, lane, aRow, bRow);

    // fused epilogue: wn==0 warps hold gate (B rows 0-127), wn==1 hold up.
    float* xbuf = (float*)sm;            // [4][32][128] f32 = 64KB
    if (wn == 1) {
#pragma unroll
        for (int mt = 0; mt < 2; mt++)
#pragma unroll
            for (int nt = 0; nt < 16; nt++)
#pragma unroll
                for (int i = 0; i < 4; i++) {
                    int rl = mt * 16 + (i >> 1) * 8 + (lane >> 2);
                    int cl = nt * 8 + (lane & 3) * 2 + (i & 1);
                    xbuf[wm * 4096 + rl * 128 + cl] = acc[mt][nt][i];
                }
    }
    __syncthreads();
    if (wn == 0) {
#pragma unroll
        for (int mt = 0; mt < 2; mt++)
#pragma unroll
            for (int rh = 0; rh < 2; rh++) {
                int rl = mt * 16 + rh * 8 + (lane >> 2);
                int gr = m0 + wr2 + rl;
                uint32_t* dh; bool ok = true;
                if (shmode) {
                    dh = g_sh2 + (size_t)gr * 1024 + (f0 >> 1);
                } else {
                    ok = gr < cnt;
                    int row = ok ? (basep + gr) : 0;
                    dh = g_eh + (size_t)row * 256 + (f0 >> 1);
                }
                if (!ok) continue;
#pragma unroll
                for (int nt = 0; nt < 16; nt++) {
                    int cc = nt * 8 + (lane & 3) * 2;
                    float gg0 = acc[mt][nt][rh * 2 + 0];
                    float gg1 = acc[mt][nt][rh * 2 + 1];
                    float u0 = xbuf[wm * 4096 + rl * 128 + cc];
                    float u1 = xbuf[wm * 4096 + rl * 128 + cc + 1];
                    float h0 = gg0 / (1.f + __expf(-gg0)) * u0;
                    float h1 = gg1 / (1.f + __expf(-gg1)) * u1;
                    __half2 hp = __floats2half2_rn(h0, h1);
                    dh[cc >> 1] = *reinterpret_cast<uint32_t*>(&hp);
                }
            }
    }
}

// ---- down GEMM (launch #5): hidden @ down^T --------------------------------
__global__ void __launch_bounds__(256, 1) k_down() {
    extern __shared__ char sm[];
    const int tid = threadIdx.x;
    const int lr = tid >> 1, lc = tid & 1, br = tid;
    const int w = tid >> 5, lane = tid & 31;
    const int wn = w & 1, wm = w >> 1;
    const int wr2 = wm * 32, wc2 = wn * 128;

    int bx = blockIdx.x;
    bool shmode; int e = 0, m0, n0, cnt = 0, basep = 0, NC;
    if (bx < 64) {
        shmode = true;
        m0 = (bx >> 2) * 128; n0 = (bx & 3) * 256; NC = 32;
    } else {
        shmode = false;
        bx -= 64;
        e = bx >> 7; int rem = bx & 127;
        m0 = (rem >> 2) * 128; n0 = (rem & 3) * 256; NC = 8;
        cnt = g_count[e]; basep = g_offset[e];
        if (m0 >= cnt) return;
    }

    const uint32_t *aRow, *bRow;
    if (shmode) {
        aRow = g_sh2 + (size_t)(m0 + lr) * 1024;
        bRow = g_d1 + (size_t)(n0 + br) * 1024;
    } else {
        int rr = m0 + lr; if (rr >= cnt) rr = cnt - 1;
        aRow = g_eh + (size_t)(basep + rr) * 256;
        bRow = g_wd + (size_t)(e * 1024 + n0 + br) * 256;
    }

    const uint32_t sb = smem_u32(sm);
    float acc[2][16][4];
#pragma unroll
    for (int a = 0; a < 2; a++)
#pragma unroll
        for (int b = 0; b < 16; b++)
#pragma unroll
            for (int c = 0; c < 4; c++) acc[a][b][c] = 0.f;

    g_mainloop(acc, sb, NC, lr, lc, br, wr2, wc2, lane, aRow, bRow);

    // epilogue
#pragma unroll
    for (int mt = 0; mt < 2; mt++) {
#pragma unroll
        for (int rh = 0; rh < 2; rh++) {
            int r = wr2 + mt * 16 + rh * 8 + (lane >> 2);
            int gr = m0 + r;
            float* dst = nullptr; float ws = 1.f; bool ok = true;
            if (shmode) {
                dst = g_shf + (size_t)gr * DDIM;
            } else {
                ok = gr < cnt;
                if (ok) { int pair = g_perm[basep + gr]; ws = g_topkw[pair]; dst = g_y + (size_t)pair * DDIM; }
            }
            if (!ok) continue;
#pragma unroll
            for (int nt = 0; nt < 16; nt++) {
                int col = n0 + wc2 + nt * 8 + (lane & 3) * 2;
                float2 v;
                v.x = acc[mt][nt][rh * 2 + 0] * ws;
                v.y = acc[mt][nt][rh * 2 + 1] * ws;
                *(float2*)(dst + col) = v;
            }
        }
    }
}

// ---- combine + aux (launch #6) ----------------------------------------------
__global__ void k_combine(float* __restrict__ out, int out_size) {
    if (blockIdx.x == gridDim.x - 1) {
        // aux-loss block (deterministic fixed-order reduction)
        __shared__ float sred[256];
        float le[EXP];
#pragma unroll
        for (int e = 0; e < EXP; e++) le[e] = 0.f;
        for (int t = threadIdx.x; t < NTOK; t += 256)
#pragma unroll
            for (int e = 0; e < EXP; e++) le[e] += g_probs[(size_t)t * EXP + e];
        float aux = 0.f;
        for (int e = 0; e < EXP; e++) {
            sred[threadIdx.x] = le[e];
            __syncthreads();
            for (int s = 128; s; s >>= 1) {
                if (threadIdx.x < s) sred[threadIdx.x] += sred[threadIdx.x + s];
                __syncthreads();
            }
            if (threadIdx.x == 0) {
                float load = sred[0] * (1.f / NTOK);
                float d = load - (1.f / EXP);
                aux += d * d;
            }
            __syncthreads();
        }
        if (threadIdx.x == 0 && out_size > NTOK * DDIM)
            out[NTOK * DDIM] = 0.001f * aux;
        return;
    }
    int i = blockIdx.x * blockDim.x + threadIdx.x;
    if (i >= NTOK * (DDIM / 4)) return;
    int t = i >> 8;
    int c = (i & 255) << 2;
    float4 y0 = *(const float4*)(g_y + (size_t)(2 * t + 0) * DDIM + c);
    float4 y1 = *(const float4*)(g_y + (size_t)(2 * t + 1) * DDIM + c);
    float4 sh = *(const float4*)(g_shf + (size_t)t * DDIM + c);
    float sg = g_sgate[t];
    float4 o;
    o.x = y0.x + y1.x + sg * sh.x;
    o.y = y0.y + y1.y + sg * sh.y;
    o.z = y0.z + y1.z + sg * sh.z;
    o.w = y0.w + y1.w + sg * sh.w;
    *(float4*)(out + (size_t)t * DDIM + c) = o;
}

// ---------------- launch -----------------------------------------------------
extern "C" void kernel_launch(void* const* d_in, const int* in_sizes, int n_in,
                              void* d_out, int out_size) {
    const float* x   = (const float*)d_in[0];   // [B,T,D]
    const float* gup = (const float*)d_in[1];   // [E,2F,D]
    const float* dwn = (const float*)d_in[2];   // [E,D,F]
    const float* rw  = (const float*)d_in[3];   // [D,E]
    const float* shg = (const float*)d_in[4];   // [D,FS]
    const float* shu = (const float*)d_in[5];   // [D,FS]
    const float* shd = (const float*)d_in[6];   // [FS,D]
    const float* sgw = (const float*)d_in[7];   // [D,1]
    float* out = (float*)d_out;

    cudaFuncSetAttribute((const void*)k_up,   cudaFuncAttributeMaxDynamicSharedMemorySize, SMBYTES);
    cudaFuncSetAttribute((const void*)k_down, cudaFuncAttributeMaxDynamicSharedMemorySize, SMBYTES);

    k_cvt_mega<<<NB_CVT, 256>>>(x, gup, dwn, shg, shu, shd);          // 1
    k_router<<<NTOK / 4, 128>>>(x, rw, sgw);                          // 2
    k_scansc<<<1, 256>>>();                                           // 3
    k_up<<<256 + EXP * 32 * 4, 256, SMBYTES>>>();                     // 4  <- profiled
    k_down<<<64 + EXP * 32 * 4, 256, SMBYTES>>>();                    // 5
    k_combine<<<(NTOK * (DDIM / 4)) / 256 + 1, 256>>>(out, out_size); // 6
}

// round 10
// speedup vs baseline: 1.1327x; 1.1327x over previous
#include <cuda_runtime.h>
#include <cuda_fp16.h>
#include <cstdint>

// Problem constants
#define NTOK 2048          // B*T
#define DDIM 1024
#define EXP  16
#define FF   512
#define FSH  2048
#define PAIRS (NTOK*2)

// ---------------- scratch (device globals) ----------------------------------
__device__ float g_probs[NTOK * EXP];
__device__ float g_topkw[PAIRS];
__device__ int   g_topki[PAIRS];
__device__ float g_sgate[NTOK];
__device__ int   g_count[EXP];
__device__ int   g_offset[EXP];
__device__ int   g_perm[PAIRS];
__device__ float g_y   [(size_t)PAIRS * DDIM];   // weighted expert outputs
__device__ float g_shf [(size_t)NTOK * DDIM];    // shared output (f32)

// fp16 packed as u32 (2 per u32), row-major [rows][K/2] u32
__device__ uint32_t g_xh [NTOK * 512];          // x       [T][D]
__device__ uint32_t g_wg [EXP * 1024 * 512];    // gup     [E*2F][D]
__device__ uint32_t g_wd [EXP * 1024 * 256];    // down    [E*D][F]
__device__ uint32_t g_g1 [FSH * 512];           // sh gate [FS][D]
__device__ uint32_t g_u1 [FSH * 512];           // sh up   [FS][D]
__device__ uint32_t g_d1 [DDIM * 1024];         // sh down [D][FS]
__device__ uint32_t g_eh [PAIRS * 256];         // exp hid [P][F]
__device__ uint32_t g_sh2[NTOK * 1024];         // sh hid  [T][FS]

// ---------------- asm helpers ------------------------------------------------
__device__ __forceinline__ uint32_t smem_u32(const void* p) {
    uint32_t a;
    asm("{ .reg .u64 t; cvta.to.shared.u64 t, %1; cvt.u32.u64 %0, t; }" : "=r"(a) : "l"(p));
    return a;
}
#define CPA(d, s) asm volatile("cp.async.cg.shared.global [%0], [%1], 16;" :: "r"(d), "l"(s) : "memory")
#define CPC()     asm volatile("cp.async.commit_group;" ::: "memory")
#define CPW2()    asm volatile("cp.async.wait_group 2;" ::: "memory")
#define CPW1()    asm volatile("cp.async.wait_group 1;" ::: "memory")
#define CPW0()    asm volatile("cp.async.wait_group 0;" ::: "memory")
#define LDSM4(r, a) \
    asm volatile("ldmatrix.sync.aligned.m8n8.x4.shared.b16 {%0,%1,%2,%3}, [%4];" \
        : "=r"((r)[0]), "=r"((r)[1]), "=r"((r)[2]), "=r"((r)[3]) : "r"(a))
#define MMA16(d, a, b0, b1) \
    asm volatile("mma.sync.aligned.m16n8k16.row.col.f32.f16.f16.f32 " \
        "{%0,%1,%2,%3},{%4,%5,%6,%7},{%8,%9},{%0,%1,%2,%3};" \
        : "+f"((d)[0]), "+f"((d)[1]), "+f"((d)[2]), "+f"((d)[3]) \
        : "r"((a)[0]), "r"((a)[1]), "r"((a)[2]), "r"((a)[3]), "r"(b0), "r"(b1))

// ---------------- mega convert kernel (launch #1) ----------------------------
#define CVT_N1 (NTOK * DDIM / 4)
#define CVT_N2 (EXP * 1024 * 1024 / 4)
#define CVT_N3 (EXP * 1024 * 512 / 4)
#define NB_STRAIGHT ((CVT_N1 + CVT_N2 + CVT_N3) / 256)   // 26624
#define NB_T_EACH   2048
#define NB_CVT (NB_STRAIGHT + 3 * NB_T_EACH)             // 32768

__global__ void k_cvt_mega(const float* __restrict__ x, const float* __restrict__ gup,
                           const float* __restrict__ dwn, const float* __restrict__ shg,
                           const float* __restrict__ shu, const float* __restrict__ shd) {
    int bx = blockIdx.x;
    int tid = threadIdx.x;
    if (bx < NB_STRAIGHT) {
        int i = bx * 256 + tid;
        const float* in; uint32_t* oh; int idx;
        if (i < CVT_N1)                { in = x;   oh = g_xh; idx = i; }
        else if (i < CVT_N1 + CVT_N2)  { in = gup; oh = g_wg; idx = i - CVT_N1; }
        else                           { in = dwn; oh = g_wd; idx = i - CVT_N1 - CVT_N2; }
        float4 v = ((const float4*)in)[idx];
        __half2 a = __floats2half2_rn(v.x, v.y);
        __half2 b = __floats2half2_rn(v.z, v.w);
        ((uint2*)oh)[idx] = make_uint2(*reinterpret_cast<uint32_t*>(&a),
                                       *reinterpret_cast<uint32_t*>(&b));
        return;
    }
    int tb = bx - NB_STRAIGHT;
    int z = tb / NB_T_EACH, r = tb % NB_T_EACH;
    const float* in; uint32_t* oh; int Kdim, Ndim, k0, n0;
    if (z == 0)      { in = shg; oh = g_g1; Kdim = DDIM; Ndim = FSH; }
    else if (z == 1) { in = shu; oh = g_u1; Kdim = DDIM; Ndim = FSH; }
    else             { in = shd; oh = g_d1; Kdim = FSH; Ndim = DDIM; }
    if (z < 2) { n0 = (r & 63) * 32; k0 = (r >> 6) * 32; }
    else       { n0 = (r & 31) * 32; k0 = (r >> 5) * 32; }
    __shared__ float tile[32][33];
    int tx = tid & 31, ty = tid >> 5;
#pragma unroll
    for (int i = 0; i < 4; i++)
        tile[ty + i * 8][tx] = in[(size_t)(k0 + ty + i * 8) * Ndim + n0 + tx];
    __syncthreads();
    int nl = tid >> 3, q = tid & 7;
    size_t orow = (size_t)(n0 + nl) * (Kdim / 2) + (k0 >> 1);
#pragma unroll
    for (int j = 0; j < 2; j++) {
        int idx = q * 2 + j, kl = idx * 2;
        __half2 h = __floats2half2_rn(tile[kl][nl], tile[kl + 1][nl]);
        oh[orow + idx] = *reinterpret_cast<uint32_t*>(&h);
    }
}

// ---------------- router (launch #2) -----------------------------------------
__global__ void k_router(const float* __restrict__ x, const float* __restrict__ rw,
                         const float* __restrict__ sgw) {
    int t = blockIdx.x * 4 + (threadIdx.x >> 5);
    int lane = threadIdx.x & 31;
    if (t >= NTOK) return;
    const float* xr = x + (size_t)t * DDIM;
    float acc[EXP];
#pragma unroll
    for (int e = 0; e < EXP; e++) acc[e] = 0.f;
    float sg = 0.f;
    for (int j = lane; j < DDIM; j += 32) {
        float xv = xr[j];
        const float* r = rw + (size_t)j * EXP;
#pragma unroll
        for (int e = 0; e < EXP; e++) acc[e] = fmaf(xv, r[e], acc[e]);
        sg = fmaf(xv, sgw[j], sg);
    }
#pragma unroll
    for (int off = 16; off; off >>= 1) {
#pragma unroll
        for (int e = 0; e < EXP; e++) acc[e] += __shfl_xor_sync(0xffffffffu, acc[e], off);
        sg += __shfl_xor_sync(0xffffffffu, sg, off);
    }
    float mx = acc[0];
#pragma unroll
    for (int e = 1; e < EXP; e++) mx = fmaxf(mx, acc[e]);
    float pr[EXP]; float sum = 0.f;
#pragma unroll
    for (int e = 0; e < EXP; e++) { pr[e] = __expf(acc[e] - mx); sum += pr[e]; }
    float inv = 1.f / sum;
#pragma unroll
    for (int e = 0; e < EXP; e++) pr[e] *= inv;
    if (lane < EXP) g_probs[(size_t)t * EXP + lane] = pr[lane];
    if (lane == 0) {
        int i1 = 0; float p1 = pr[0];
#pragma unroll
        for (int e = 1; e < EXP; e++) if (pr[e] > p1) { p1 = pr[e]; i1 = e; }
        int i2 = (i1 == 0) ? 1 : 0; float p2 = pr[i2];
#pragma unroll
        for (int e = 0; e < EXP; e++) if (e != i1 && pr[e] > p2) { p2 = pr[e]; i2 = e; }
        float s2 = p1 + p2; if (s2 < 1e-9f) s2 = 1e-9f;
        g_topkw[t * 2 + 0] = p1 / s2;  g_topkw[t * 2 + 1] = p2 / s2;
        g_topki[t * 2 + 0] = i1;       g_topki[t * 2 + 1] = i2;
        g_sgate[t] = 1.f / (1.f + __expf(-sg));
    }
}

// ---------------- deterministic scan+scatter (launch #3, 1 block) ------------
__global__ void k_scansc() {
    __shared__ int hist[256][EXP];
    __shared__ int s_cnt[EXP], s_off[EXP];
    int tid = threadIdx.x;
    int lo = tid * 16;
    int h[EXP];
#pragma unroll
    for (int e = 0; e < EXP; e++) h[e] = 0;
    int el[16];
#pragma unroll
    for (int j = 0; j < 16; j++) { el[j] = g_topki[lo + j]; h[el[j]]++; }
#pragma unroll
    for (int e = 0; e < EXP; e++) hist[tid][e] = h[e];
    __syncthreads();
    if (tid < EXP) {
        int run = 0;
        for (int t = 0; t < 256; t++) { int v = hist[t][tid]; hist[t][tid] = run; run += v; }
        s_cnt[tid] = run;
    }
    __syncthreads();
    if (tid == 0) {
        int s = 0;
        for (int e = 0; e < EXP; e++) {
            s_off[e] = s; g_offset[e] = s; g_count[e] = s_cnt[e]; s += s_cnt[e];
        }
    }
    __syncthreads();
    int run[EXP];
#pragma unroll
    for (int e = 0; e < EXP; e++) run[e] = s_off[e] + hist[tid][e];
#pragma unroll
    for (int j = 0; j < 16; j++) {
        int e = el[j];
        g_perm[run[e]++] = lo + j;
    }
}

// ------- HMMA GEMM core: 128x256 tile, BK=64, 512 threads (16 warps) --------
#define ROWB   144              // bytes per smem row (64 halfs + 8 pad)
#define A_BYTES (128 * ROWB)    // 18432
#define B_BYTES (256 * ROWB)    // 36864
#define STAGE  (A_BYTES + B_BYTES)  // 55296
#define NSTG   4
#define SMBYTES (NSTG * STAGE)  // 221184

// loaders: A thread ar=tid>>2 (0..127), ac=tid&3 (2x16B); B br=tid>>1, bc=tid&1 (4x16B)
__device__ __forceinline__ void g_load(uint32_t sb, int s, int c, int ar, int ac,
                                       int bc, const uint32_t* aRow, const uint32_t* bRow) {
    uint32_t stg = sb + s * STAGE;
    uint32_t ad = stg + ar * ROWB + ac * 32;
    const uint32_t* as = aRow + c * 32 + ac * 8;
    CPA(ad, as);
    CPA(ad + 16, as + 4);
    uint32_t bd = stg + A_BYTES + (0) ;  // placeholder unused
    (void)bd;
    uint32_t bdd = stg + A_BYTES + ( ( (ar << 2) | ac ) >> 1 ) * ROWB;  // br = tid>>1
    const uint32_t* bs = bRow + c * 32 + bc * 16;
    uint32_t bb = bdd + bc * 64;
#pragma unroll
    for (int i = 0; i < 4; i++) CPA(bb + i * 16, bs + i * 4);
}

// mainloop: 4-stage pipeline, 16 warps (4m x 4n), warp tile 32x64, acc[2][8][4]
__device__ __forceinline__ void g_mainloop(float acc[2][8][4], uint32_t sb, int NC,
                                           int ar, int ac, int bc, int wr, int wc, int lane,
                                           const uint32_t* aRow, const uint32_t* bRow) {
    g_load(sb, 0, 0, ar, ac, bc, aRow, bRow); CPC();
    if (NC > 1) { g_load(sb, 1, 1, ar, ac, bc, aRow, bRow); CPC(); }
    if (NC > 2) { g_load(sb, 2, 2, ar, ac, bc, aRow, bRow); CPC(); }
    for (int c = 0; c < NC; c++) {
        int rem = NC - c;
        if (rem >= 3) CPW2(); else if (rem == 2) CPW1(); else CPW0();
        __syncthreads();
        if (c + 3 < NC) { g_load(sb, (c + 3) & 3, c + 3, ar, ac, bc, aRow, bRow); CPC(); }
        uint32_t stg = sb + (c & 3) * STAGE;
#pragma unroll
        for (int ks = 0; ks < 4; ks++) {
            int ko = ks * 32;
            uint32_t ah[2][4];
#pragma unroll
            for (int mt = 0; mt < 2; mt++) {
                uint32_t ad = stg + (wr + mt * 16 + (lane & 15)) * ROWB + ko + (lane >> 4) * 16;
                LDSM4(ah[mt], ad);
            }
            uint32_t bh[4][4];
#pragma unroll
            for (int p = 0; p < 4; p++) {
                uint32_t bd = stg + A_BYTES + (wc + p * 16 + (lane & 15)) * ROWB + ko + (lane >> 4) * 16;
                LDSM4(bh[p], bd);
            }
#pragma unroll
            for (int mt = 0; mt < 2; mt++)
#pragma unroll
                for (int p = 0; p < 4; p++) {
                    MMA16(acc[mt][2 * p],     ah[mt], bh[p][0], bh[p][2]);
                    MMA16(acc[mt][2 * p + 1], ah[mt], bh[p][1], bh[p][3]);
                }
        }
    }
    __syncthreads();   // smem reused by epilogue
}

// ---- up GEMM (launch #4): x @ {gate,up}^T fused silu*up -> fp16 hidden -----
// B tile: rows 0-127 = gate (128 f cols), rows 128-255 = up (same f cols).
__global__ void __launch_bounds__(512, 1) k_up() {
    extern __shared__ char sm[];
    const int tid = threadIdx.x;
    const int ar = tid >> 2, ac = tid & 3, bc = tid & 1;
    const int w = tid >> 5, lane = tid & 31;
    const int wn = w & 3, wm = w >> 2;          // wm 0..3 (m), wn 0..3 (n)
    const int wr2 = wm * 32, wc2 = wn * 64;

    int bx = blockIdx.x;
    bool shmode; int e = 0, m0, f0, cnt = 0, basep = 0;
    if (bx < 256) {
        shmode = true;
        m0 = (bx >> 4) * 128; f0 = (bx & 15) * 128;
    } else {
        shmode = false;
        bx -= 256;
        e = bx >> 7; int rem = bx & 127;
        m0 = (rem >> 2) * 128; f0 = (rem & 3) * 128;
        cnt = g_count[e]; basep = g_offset[e];
        if (m0 >= cnt) return;
    }

    const int br = tid >> 1;    // B row this thread loads
    const uint32_t *aRow, *bRow;
    if (shmode) {
        aRow = g_xh + (size_t)(m0 + ar) * 512;
        bRow = (br < 128) ? g_g1 + (size_t)(f0 + br) * 512
                          : g_u1 + (size_t)(f0 + br - 128) * 512;
    } else {
        int rr = m0 + ar; if (rr >= cnt) rr = cnt - 1;
        int token = g_perm[basep + rr] >> 1;
        aRow = g_xh + (size_t)token * 512;
        int brow = (br < 128) ? (e * 1024 + f0 + br) : (e * 1024 + 512 + f0 + br - 128);
        bRow = g_wg + (size_t)brow * 512;
    }

    const uint32_t sb = smem_u32(sm);
    float acc[2][8][4];
#pragma unroll
    for (int a = 0; a < 2; a++)
#pragma unroll
        for (int b = 0; b < 8; b++)
#pragma unroll
            for (int c = 0; c < 4; c++) acc[a][b][c] = 0.f;

    g_mainloop(acc, sb, 16, ar, ac, bc, wr2, wc2, lane, aRow, bRow);

    // fused epilogue: wn 0,1 hold gate cols (B rows 0-127); wn 2,3 hold up.
    float* xbuf = (float*)sm;            // [4][32][128] f32 = 64KB
    if (wn >= 2) {
#pragma unroll
        for (int mt = 0; mt < 2; mt++)
#pragma unroll
            for (int nt = 0; nt < 8; nt++)
#pragma unroll
                for (int i = 0; i < 4; i++) {
                    int rl = mt * 16 + (i >> 1) * 8 + (lane >> 2);
                    int cl = (wn - 2) * 64 + nt * 8 + (lane & 3) * 2 + (i & 1);
                    xbuf[wm * 4096 + rl * 128 + cl] = acc[mt][nt][i];
                }
    }
    __syncthreads();
    if (wn < 2) {
#pragma unroll
        for (int mt = 0; mt < 2; mt++)
#pragma unroll
            for (int rh = 0; rh < 2; rh++) {
                int rl = mt * 16 + rh * 8 + (lane >> 2);
                int gr = m0 + wm * 32 + rl;
                uint32_t* dh; bool ok = true;
                if (shmode) {
                    dh = g_sh2 + (size_t)gr * 1024 + (f0 >> 1);
                } else {
                    ok = gr < cnt;
                    int row = ok ? (basep + gr) : 0;
                    dh = g_eh + (size_t)row * 256 + (f0 >> 1);
                }
                if (!ok) continue;
#pragma unroll
                for (int nt = 0; nt < 8; nt++) {
                    int cc = wn * 64 + nt * 8 + (lane & 3) * 2;
                    float gg0 = acc[mt][nt][rh * 2 + 0];
                    float gg1 = acc[mt][nt][rh * 2 + 1];
                    float u0 = xbuf[wm * 4096 + rl * 128 + cc];
                    float u1 = xbuf[wm * 4096 + rl * 128 + cc + 1];
                    float h0 = gg0 / (1.f + __expf(-gg0)) * u0;
                    float h1 = gg1 / (1.f + __expf(-gg1)) * u1;
                    __half2 hp = __floats2half2_rn(h0, h1);
                    dh[cc >> 1] = *reinterpret_cast<uint32_t*>(&hp);
                }
            }
    }
}

// ---- down GEMM (launch #5): hidden @ down^T --------------------------------
__global__ void __launch_bounds__(512, 1) k_down() {
    extern __shared__ char sm[];
    const int tid = threadIdx.x;
    const int ar = tid >> 2, ac = tid & 3, bc = tid & 1;
    const int w = tid >> 5, lane = tid & 31;
    const int wn = w & 3, wm = w >> 2;
    const int wr2 = wm * 32, wc2 = wn * 64;

    int bx = blockIdx.x;
    bool shmode; int e = 0, m0, n0, cnt = 0, basep = 0, NC;
    if (bx < 64) {
        shmode = true;
        m0 = (bx >> 2) * 128; n0 = (bx & 3) * 256; NC = 32;
    } else {
        shmode = false;
        bx -= 64;
        e = bx >> 7; int rem = bx & 127;
        m0 = (rem >> 2) * 128; n0 = (rem & 3) * 256; NC = 8;
        cnt = g_count[e]; basep = g_offset[e];
        if (m0 >= cnt) return;
    }

    const int br = tid >> 1;
    const uint32_t *aRow, *bRow;
    if (shmode) {
        aRow = g_sh2 + (size_t)(m0 + ar) * 1024;
        bRow = g_d1 + (size_t)(n0 + br) * 1024;
    } else {
        int rr = m0 + ar; if (rr >= cnt) rr = cnt - 1;
        aRow = g_eh + (size_t)(basep + rr) * 256;
        bRow = g_wd + (size_t)(e * 1024 + n0 + br) * 256;
    }

    const uint32_t sb = smem_u32(sm);
    float acc[2][8][4];
#pragma unroll
    for (int a = 0; a < 2; a++)
#pragma unroll
        for (int b = 0; b < 8; b++)
#pragma unroll
            for (int c = 0; c < 4; c++) acc[a][b][c] = 0.f;

    g_mainloop(acc, sb, NC, ar, ac, bc, wr2, wc2, lane, aRow, bRow);

    // epilogue
#pragma unroll
    for (int mt = 0; mt < 2; mt++) {
#pragma unroll
        for (int rh = 0; rh < 2; rh++) {
            int r = wr2 + mt * 16 + rh * 8 + (lane >> 2);
            int gr = m0 + r;
            float* dst = nullptr; float ws = 1.f; bool ok = true;
            if (shmode) {
                dst = g_shf + (size_t)gr * DDIM;
            } else {
                ok = gr < cnt;
                if (ok) { int pair = g_perm[basep + gr]; ws = g_topkw[pair]; dst = g_y + (size_t)pair * DDIM; }
            }
            if (!ok) continue;
#pragma unroll
            for (int nt = 0; nt < 8; nt++) {
                int col = n0 + wc2 + nt * 8 + (lane & 3) * 2;
                float2 v;
                v.x = acc[mt][nt][rh * 2 + 0] * ws;
                v.y = acc[mt][nt][rh * 2 + 1] * ws;
                *(float2*)(dst + col) = v;
            }
        }
    }
}

// ---- combine + aux (launch #6) ----------------------------------------------
__global__ void k_combine(float* __restrict__ out, int out_size) {
    if (blockIdx.x == gridDim.x - 1) {
        __shared__ float sred[256];
        float le[EXP];
#pragma unroll
        for (int e = 0; e < EXP; e++) le[e] = 0.f;
        for (int t = threadIdx.x; t < NTOK; t += 256)
#pragma unroll
            for (int e = 0; e < EXP; e++) le[e] += g_probs[(size_t)t * EXP + e];
        float aux = 0.f;
        for (int e = 0; e < EXP; e++) {
            sred[threadIdx.x] = le[e];
            __syncthreads();
            for (int s = 128; s; s >>= 1) {
                if (threadIdx.x < s) sred[threadIdx.x] += sred[threadIdx.x + s];
                __syncthreads();
            }
            if (threadIdx.x == 0) {
                float load = sred[0] * (1.f / NTOK);
                float d = load - (1.f / EXP);
                aux += d * d;
            }
            __syncthreads();
        }
        if (threadIdx.x == 0 && out_size > NTOK * DDIM)
            out[NTOK * DDIM] = 0.001f * aux;
        return;
    }
    int i = blockIdx.x * blockDim.x + threadIdx.x;
    if (i >= NTOK * (DDIM / 4)) return;
    int t = i >> 8;
    int c = (i & 255) << 2;
    float4 y0 = *(const float4*)(g_y + (size_t)(2 * t + 0) * DDIM + c);
    float4 y1 = *(const float4*)(g_y + (size_t)(2 * t + 1) * DDIM + c);
    float4 sh = *(const float4*)(g_shf + (size_t)t * DDIM + c);
    float sg = g_sgate[t];
    float4 o;
    o.x = y0.x + y1.x + sg * sh.x;
    o.y = y0.y + y1.y + sg * sh.y;
    o.z = y0.z + y1.z + sg * sh.z;
    o.w = y0.w + y1.w + sg * sh.w;
    *(float4*)(out + (size_t)t * DDIM + c) = o;
}

// ---------------- launch -----------------------------------------------------
extern "C" void kernel_launch(void* const* d_in, const int* in_sizes, int n_in,
                              void* d_out, int out_size) {
    const float* x   = (const float*)d_in[0];   // [B,T,D]
    const float* gup = (const float*)d_in[1];   // [E,2F,D]
    const float* dwn = (const float*)d_in[2];   // [E,D,F]
    const float* rw  = (const float*)d_in[3];   // [D,E]
    const float* shg = (const float*)d_in[4];   // [D,FS]
    const float* shu = (const float*)d_in[5];   // [D,FS]
    const float* shd = (const float*)d_in[6];   // [FS,D]
    const float* sgw = (const float*)d_in[7];   // [D,1]
    float* out = (float*)d_out;

    cudaFuncSetAttribute((const void*)k_up,   cudaFuncAttributeMaxDynamicSharedMemorySize, SMBYTES);
    cudaFuncSetAttribute((const void*)k_down, cudaFuncAttributeMaxDynamicSharedMemorySize, SMBYTES);

    k_cvt_mega<<<NB_CVT, 256>>>(x, gup, dwn, shg, shu, shd);          // 1
    k_router<<<NTOK / 4, 128>>>(x, rw, sgw);                          // 2
    k_scansc<<<1, 256>>>();                                           // 3
    k_up<<<256 + EXP * 32 * 4, 512, SMBYTES>>>();                     // 4  <- profiled
    k_down<<<64 + EXP * 32 * 4, 512, SMBYTES>>>();                    // 5
    k_combine<<<(NTOK * (DDIM / 4)) / 256 + 1, 256>>>(out, out_size); // 6
}

// round 11
// speedup vs baseline: 1.1440x; 1.0099x over previous
#include <cuda_runtime.h>
#include <cuda_fp16.h>
#include <cstdint>

// Problem constants
#define NTOK 2048          // B*T
#define DDIM 1024
#define EXP  16
#define FF   512
#define FSH  2048
#define PAIRS (NTOK*2)

// ---------------- scratch (device globals) ----------------------------------
__device__ float g_probs[NTOK * EXP];
__device__ float g_topkw[PAIRS];
__device__ int   g_topki[PAIRS];
__device__ float g_sgate[NTOK];
__device__ int   g_count[EXP];
__device__ int   g_offset[EXP];
__device__ int   g_perm[PAIRS];
__device__ float g_y   [(size_t)PAIRS * DDIM];   // weighted expert outputs
__device__ float g_shf [(size_t)NTOK * DDIM];    // shared output (f32)

// fp16 packed as u32 (2 per u32), row-major [rows][K/2] u32
__device__ uint32_t g_xh [NTOK * 512];          // x       [T][D]
__device__ uint32_t g_wg [EXP * 1024 * 512];    // gup     [E*2F][D]
__device__ uint32_t g_wd [EXP * 1024 * 256];    // down    [E*D][F]
__device__ uint32_t g_g1 [FSH * 512];           // sh gate [FS][D]
__device__ uint32_t g_u1 [FSH * 512];           // sh up   [FS][D]
__device__ uint32_t g_d1 [DDIM * 1024];         // sh down [D][FS]
__device__ uint32_t g_eh [PAIRS * 256];         // exp hid [P][F]
__device__ uint32_t g_sh2[NTOK * 1024];         // sh hid  [T][FS]

// ---------------- asm helpers ------------------------------------------------
__device__ __forceinline__ uint32_t smem_u32(const void* p) {
    uint32_t a;
    asm("{ .reg .u64 t; cvta.to.shared.u64 t, %1; cvt.u32.u64 %0, t; }" : "=r"(a) : "l"(p));
    return a;
}
#define CPA(d, s) asm volatile("cp.async.cg.shared.global [%0], [%1], 16;" :: "r"(d), "l"(s) : "memory")
#define CPC()     asm volatile("cp.async.commit_group;" ::: "memory")
#define CPW2()    asm volatile("cp.async.wait_group 2;" ::: "memory")
#define CPW1()    asm volatile("cp.async.wait_group 1;" ::: "memory")
#define CPW0()    asm volatile("cp.async.wait_group 0;" ::: "memory")
#define LDSM4(r, a) \
    asm volatile("ldmatrix.sync.aligned.m8n8.x4.shared.b16 {%0,%1,%2,%3}, [%4];" \
        : "=r"((r)[0]), "=r"((r)[1]), "=r"((r)[2]), "=r"((r)[3]) : "r"(a))
#define MMA16(d, a, b0, b1) \
    asm volatile("mma.sync.aligned.m16n8k16.row.col.f32.f16.f16.f32 " \
        "{%0,%1,%2,%3},{%4,%5,%6,%7},{%8,%9},{%0,%1,%2,%3};" \
        : "+f"((d)[0]), "+f"((d)[1]), "+f"((d)[2]), "+f"((d)[3]) \
        : "r"((a)[0]), "r"((a)[1]), "r"((a)[2]), "r"((a)[3]), "r"(b0), "r"(b1))

// ---------------- mega convert kernel (launch #1) ----------------------------
#define CVT_N1 (NTOK * DDIM / 4)
#define CVT_N2 (EXP * 1024 * 1024 / 4)
#define CVT_N3 (EXP * 1024 * 512 / 4)
#define NB_STRAIGHT ((CVT_N1 + CVT_N2 + CVT_N3) / 256)   // 26624
#define NB_T_EACH   2048
#define NB_CVT (NB_STRAIGHT + 3 * NB_T_EACH)             // 32768

__global__ void k_cvt_mega(const float* __restrict__ x, const float* __restrict__ gup,
                           const float* __restrict__ dwn, const float* __restrict__ shg,
                           const float* __restrict__ shu, const float* __restrict__ shd) {
    int bx = blockIdx.x;
    int tid = threadIdx.x;
    if (bx < NB_STRAIGHT) {
        int i = bx * 256 + tid;
        const float* in; uint32_t* oh; int idx;
        if (i < CVT_N1)                { in = x;   oh = g_xh; idx = i; }
        else if (i < CVT_N1 + CVT_N2)  { in = gup; oh = g_wg; idx = i - CVT_N1; }
        else                           { in = dwn; oh = g_wd; idx = i - CVT_N1 - CVT_N2; }
        float4 v = ((const float4*)in)[idx];
        __half2 a = __floats2half2_rn(v.x, v.y);
        __half2 b = __floats2half2_rn(v.z, v.w);
        ((uint2*)oh)[idx] = make_uint2(*reinterpret_cast<uint32_t*>(&a),
                                       *reinterpret_cast<uint32_t*>(&b));
        return;
    }
    int tb = bx - NB_STRAIGHT;
    int z = tb / NB_T_EACH, r = tb % NB_T_EACH;
    const float* in; uint32_t* oh; int Kdim, Ndim, k0, n0;
    if (z == 0)      { in = shg; oh = g_g1; Kdim = DDIM; Ndim = FSH; }
    else if (z == 1) { in = shu; oh = g_u1; Kdim = DDIM; Ndim = FSH; }
    else             { in = shd; oh = g_d1; Kdim = FSH; Ndim = DDIM; }
    if (z < 2) { n0 = (r & 63) * 32; k0 = (r >> 6) * 32; }
    else       { n0 = (r & 31) * 32; k0 = (r >> 5) * 32; }
    __shared__ float tile[32][33];
    int tx = tid & 31, ty = tid >> 5;
#pragma unroll
    for (int i = 0; i < 4; i++)
        tile[ty + i * 8][tx] = in[(size_t)(k0 + ty + i * 8) * Ndim + n0 + tx];
    __syncthreads();
    int nl = tid >> 3, q = tid & 7;
    size_t orow = (size_t)(n0 + nl) * (Kdim / 2) + (k0 >> 1);
#pragma unroll
    for (int j = 0; j < 2; j++) {
        int idx = q * 2 + j, kl = idx * 2;
        __half2 h = __floats2half2_rn(tile[kl][nl], tile[kl + 1][nl]);
        oh[orow + idx] = *reinterpret_cast<uint32_t*>(&h);
    }
}

// ---------------- router (launch #2) -----------------------------------------
__global__ void k_router(const float* __restrict__ x, const float* __restrict__ rw,
                         const float* __restrict__ sgw) {
    int t = blockIdx.x * 4 + (threadIdx.x >> 5);
    int lane = threadIdx.x & 31;
    if (t >= NTOK) return;
    const float* xr = x + (size_t)t * DDIM;
    float acc[EXP];
#pragma unroll
    for (int e = 0; e < EXP; e++) acc[e] = 0.f;
    float sg = 0.f;
    for (int j = lane; j < DDIM; j += 32) {
        float xv = xr[j];
        const float* r = rw + (size_t)j * EXP;
#pragma unroll
        for (int e = 0; e < EXP; e++) acc[e] = fmaf(xv, r[e], acc[e]);
        sg = fmaf(xv, sgw[j], sg);
    }
#pragma unroll
    for (int off = 16; off; off >>= 1) {
#pragma unroll
        for (int e = 0; e < EXP; e++) acc[e] += __shfl_xor_sync(0xffffffffu, acc[e], off);
        sg += __shfl_xor_sync(0xffffffffu, sg, off);
    }
    float mx = acc[0];
#pragma unroll
    for (int e = 1; e < EXP; e++) mx = fmaxf(mx, acc[e]);
    float pr[EXP]; float sum = 0.f;
#pragma unroll
    for (int e = 0; e < EXP; e++) { pr[e] = __expf(acc[e] - mx); sum += pr[e]; }
    float inv = 1.f / sum;
#pragma unroll
    for (int e = 0; e < EXP; e++) pr[e] *= inv;
    if (lane < EXP) g_probs[(size_t)t * EXP + lane] = pr[lane];
    if (lane == 0) {
        int i1 = 0; float p1 = pr[0];
#pragma unroll
        for (int e = 1; e < EXP; e++) if (pr[e] > p1) { p1 = pr[e]; i1 = e; }
        int i2 = (i1 == 0) ? 1 : 0; float p2 = pr[i2];
#pragma unroll
        for (int e = 0; e < EXP; e++) if (e != i1 && pr[e] > p2) { p2 = pr[e]; i2 = e; }
        float s2 = p1 + p2; if (s2 < 1e-9f) s2 = 1e-9f;
        g_topkw[t * 2 + 0] = p1 / s2;  g_topkw[t * 2 + 1] = p2 / s2;
        g_topki[t * 2 + 0] = i1;       g_topki[t * 2 + 1] = i2;
        g_sgate[t] = 1.f / (1.f + __expf(-sg));
    }
}

// ---------------- deterministic scan+scatter (launch #3, 1 block) ------------
__global__ void k_scansc() {
    __shared__ int hist[256][EXP];
    __shared__ int s_cnt[EXP], s_off[EXP];
    int tid = threadIdx.x;
    int lo = tid * 16;
    int h[EXP];
#pragma unroll
    for (int e = 0; e < EXP; e++) h[e] = 0;
    int el[16];
#pragma unroll
    for (int j = 0; j < 16; j++) { el[j] = g_topki[lo + j]; h[el[j]]++; }
#pragma unroll
    for (int e = 0; e < EXP; e++) hist[tid][e] = h[e];
    __syncthreads();
    if (tid < EXP) {
        int run = 0;
        for (int t = 0; t < 256; t++) { int v = hist[t][tid]; hist[t][tid] = run; run += v; }
        s_cnt[tid] = run;
    }
    __syncthreads();
    if (tid == 0) {
        int s = 0;
        for (int e = 0; e < EXP; e++) {
            s_off[e] = s; g_offset[e] = s; g_count[e] = s_cnt[e]; s += s_cnt[e];
        }
    }
    __syncthreads();
    int run[EXP];
#pragma unroll
    for (int e = 0; e < EXP; e++) run[e] = s_off[e] + hist[tid][e];
#pragma unroll
    for (int j = 0; j < 16; j++) {
        int e = el[j];
        g_perm[run[e]++] = lo + j;
    }
}

// ------- HMMA GEMM core: 128x256 tile, BK=64, 512 threads (16 warps) --------
#define ROWB   144              // bytes per smem row (64 halfs + 8 pad)
#define A_BYTES (128 * ROWB)    // 18432
#define B_BYTES (256 * ROWB)    // 36864
#define STAGE  (A_BYTES + B_BYTES)  // 55296
#define NSTG   4
#define SMBYTES (NSTG * STAGE)  // 221184

// loaders: A thread ar=tid>>2 (0..127), ac=tid&3 (2x16B); B br=tid>>1, bc=tid&1 (4x16B)
__device__ __forceinline__ void g_load(uint32_t sb, int s, int c, int ar, int ac,
                                       int bc, const uint32_t* aRow, const uint32_t* bRow) {
    uint32_t stg = sb + s * STAGE;
    uint32_t ad = stg + ar * ROWB + ac * 32;
    const uint32_t* as = aRow + c * 32 + ac * 8;
    CPA(ad, as);
    CPA(ad + 16, as + 4);
    uint32_t bdd = stg + A_BYTES + (((ar << 2) | ac) >> 1) * ROWB;  // br = tid>>1
    const uint32_t* bs = bRow + c * 32 + bc * 16;
    uint32_t bb = bdd + bc * 64;
#pragma unroll
    for (int i = 0; i < 4; i++) CPA(bb + i * 16, bs + i * 4);
}

// mainloop: 4-stage gmem pipeline + B-fragment software pipeline.
// 16 warps (4m x 4n), warp tile 32x64, acc[2][8][4]
__device__ __forceinline__ void g_mainloop(float acc[2][8][4], uint32_t sb, int NC,
                                           int ar, int ac, int bc, int wr, int wc, int lane,
                                           const uint32_t* aRow, const uint32_t* bRow) {
    g_load(sb, 0, 0, ar, ac, bc, aRow, bRow); CPC();
    if (NC > 1) { g_load(sb, 1, 1, ar, ac, bc, aRow, bRow); CPC(); }
    if (NC > 2) { g_load(sb, 2, 2, ar, ac, bc, aRow, bRow); CPC(); }
    // per-warp fragment smem offsets (stage-relative)
    const uint32_t awoff = (uint32_t)((wr + (lane & 15)) * ROWB + (lane >> 4) * 16);
    const uint32_t bwoff = (uint32_t)(A_BYTES + (wc + (lane & 15)) * ROWB + (lane >> 4) * 16);
    for (int c = 0; c < NC; c++) {
        int rem = NC - c;
        if (rem >= 3) CPW2(); else if (rem == 2) CPW1(); else CPW0();
        __syncthreads();
        if (c + 3 < NC) { g_load(sb, (c + 3) & 3, c + 3, ar, ac, bc, aRow, bRow); CPC(); }
        uint32_t stg = sb + (c & 3) * STAGE;
#pragma unroll
        for (int ks = 0; ks < 4; ks++) {
            int ko = ks * 32;
            uint32_t aw = stg + awoff + ko;
            uint32_t bw = stg + bwoff + ko;
            uint32_t ah[2][4];
            LDSM4(ah[0], aw);
            LDSM4(ah[1], aw + 16 * ROWB);
            uint32_t bcur[4], bnxt[4];
            LDSM4(bcur, bw);
#pragma unroll
            for (int p = 0; p < 4; p++) {
                if (p < 3) LDSM4(bnxt, bw + (p + 1) * 16 * ROWB);
                MMA16(acc[0][2 * p],     ah[0], bcur[0], bcur[2]);
                MMA16(acc[0][2 * p + 1], ah[0], bcur[1], bcur[3]);
                MMA16(acc[1][2 * p],     ah[1], bcur[0], bcur[2]);
                MMA16(acc[1][2 * p + 1], ah[1], bcur[1], bcur[3]);
#pragma unroll
                for (int q = 0; q < 4; q++) bcur[q] = bnxt[q];
            }
        }
    }
    __syncthreads();   // smem reused by epilogue
}

// ---- up GEMM (launch #4): x @ {gate,up}^T fused silu*up -> fp16 hidden -----
// B tile: rows 0-127 = gate (128 f cols), rows 128-255 = up (same f cols).
__global__ void __launch_bounds__(512, 1) k_up() {
    extern __shared__ char sm[];
    const int tid = threadIdx.x;
    const int ar = tid >> 2, ac = tid & 3, bc = tid & 1;
    const int w = tid >> 5, lane = tid & 31;
    const int wn = w & 3, wm = w >> 2;          // wm 0..3 (m), wn 0..3 (n)
    const int wr2 = wm * 32, wc2 = wn * 64;

    int bx = blockIdx.x;
    bool shmode; int e = 0, m0, f0, cnt = 0, basep = 0;
    if (bx < 256) {
        shmode = true;
        m0 = (bx >> 4) * 128; f0 = (bx & 15) * 128;
    } else {
        shmode = false;
        bx -= 256;
        e = bx >> 7; int rem = bx & 127;
        m0 = (rem >> 2) * 128; f0 = (rem & 3) * 128;
        cnt = g_count[e]; basep = g_offset[e];
        if (m0 >= cnt) return;
    }

    const int br = tid >> 1;    // B row this thread loads
    const uint32_t *aRow, *bRow;
    if (shmode) {
        aRow = g_xh + (size_t)(m0 + ar) * 512;
        bRow = (br < 128) ? g_g1 + (size_t)(f0 + br) * 512
                          : g_u1 + (size_t)(f0 + br - 128) * 512;
    } else {
        int rr = m0 + ar; if (rr >= cnt) rr = cnt - 1;
        int token = g_perm[basep + rr] >> 1;
        aRow = g_xh + (size_t)token * 512;
        int brow = (br < 128) ? (e * 1024 + f0 + br) : (e * 1024 + 512 + f0 + br - 128);
        bRow = g_wg + (size_t)brow * 512;
    }

    const uint32_t sb = smem_u32(sm);
    float acc[2][8][4];
#pragma unroll
    for (int a = 0; a < 2; a++)
#pragma unroll
        for (int b = 0; b < 8; b++)
#pragma unroll
            for (int c = 0; c < 4; c++) acc[a][b][c] = 0.f;

    g_mainloop(acc, sb, 16, ar, ac, bc, wr2, wc2, lane, aRow, bRow);

    // fused epilogue: wn 0,1 hold gate cols (B rows 0-127); wn 2,3 hold up.
    float* xbuf = (float*)sm;            // [4][32][128] f32 = 64KB
    if (wn >= 2) {
#pragma unroll
        for (int mt = 0; mt < 2; mt++)
#pragma unroll
            for (int nt = 0; nt < 8; nt++)
#pragma unroll
                for (int i = 0; i < 4; i++) {
                    int rl = mt * 16 + (i >> 1) * 8 + (lane >> 2);
                    int cl = (wn - 2) * 64 + nt * 8 + (lane & 3) * 2 + (i & 1);
                    xbuf[wm * 4096 + rl * 128 + cl] = acc[mt][nt][i];
                }
    }
    __syncthreads();
    if (wn < 2) {
#pragma unroll
        for (int mt = 0; mt < 2; mt++)
#pragma unroll
            for (int rh = 0; rh < 2; rh++) {
                int rl = mt * 16 + rh * 8 + (lane >> 2);
                int gr = m0 + wm * 32 + rl;
                uint32_t* dh; bool ok = true;
                if (shmode) {
                    dh = g_sh2 + (size_t)gr * 1024 + (f0 >> 1);
                } else {
                    ok = gr < cnt;
                    int row = ok ? (basep + gr) : 0;
                    dh = g_eh + (size_t)row * 256 + (f0 >> 1);
                }
                if (!ok) continue;
#pragma unroll
                for (int nt = 0; nt < 8; nt++) {
                    int cc = wn * 64 + nt * 8 + (lane & 3) * 2;
                    float gg0 = acc[mt][nt][rh * 2 + 0];
                    float gg1 = acc[mt][nt][rh * 2 + 1];
                    float u0 = xbuf[wm * 4096 + rl * 128 + cc];
                    float u1 = xbuf[wm * 4096 + rl * 128 + cc + 1];
                    float h0 = gg0 / (1.f + __expf(-gg0)) * u0;
                    float h1 = gg1 / (1.f + __expf(-gg1)) * u1;
                    __half2 hp = __floats2half2_rn(h0, h1);
                    dh[cc >> 1] = *reinterpret_cast<uint32_t*>(&hp);
                }
            }
    }
}

// ---- down GEMM (launch #5): hidden @ down^T --------------------------------
__global__ void __launch_bounds__(512, 1) k_down() {
    extern __shared__ char sm[];
    const int tid = threadIdx.x;
    const int ar = tid >> 2, ac = tid & 3, bc = tid & 1;
    const int w = tid >> 5, lane = tid & 31;
    const int wn = w & 3, wm = w >> 2;
    const int wr2 = wm * 32, wc2 = wn * 64;

    int bx = blockIdx.x;
    bool shmode; int e = 0, m0, n0, cnt = 0, basep = 0, NC;
    if (bx < 64) {
        shmode = true;
        m0 = (bx >> 2) * 128; n0 = (bx & 3) * 256; NC = 32;
    } else {
        shmode = false;
        bx -= 64;
        e = bx >> 7; int rem = bx & 127;
        m0 = (rem >> 2) * 128; n0 = (rem & 3) * 256; NC = 8;
        cnt = g_count[e]; basep = g_offset[e];
        if (m0 >= cnt) return;
    }

    const int br = tid >> 1;
    const uint32_t *aRow, *bRow;
    if (shmode) {
        aRow = g_sh2 + (size_t)(m0 + ar) * 1024;
        bRow = g_d1 + (size_t)(n0 + br) * 1024;
    } else {
        int rr = m0 + ar; if (rr >= cnt) rr = cnt - 1;
        aRow = g_eh + (size_t)(basep + rr) * 256;
        bRow = g_wd + (size_t)(e * 1024 + n0 + br) * 256;
    }

    const uint32_t sb = smem_u32(sm);
    float acc[2][8][4];
#pragma unroll
    for (int a = 0; a < 2; a++)
#pragma unroll
        for (int b = 0; b < 8; b++)
#pragma unroll
            for (int c = 0; c < 4; c++) acc[a][b][c] = 0.f;

    g_mainloop(acc, sb, NC, ar, ac, bc, wr2, wc2, lane, aRow, bRow);

    // epilogue
#pragma unroll
    for (int mt = 0; mt < 2; mt++) {
#pragma unroll
        for (int rh = 0; rh < 2; rh++) {
            int r = wr2 + mt * 16 + rh * 8 + (lane >> 2);
            int gr = m0 + r;
            float* dst = nullptr; float ws = 1.f; bool ok = true;
            if (shmode) {
                dst = g_shf + (size_t)gr * DDIM;
            } else {
                ok = gr < cnt;
                if (ok) { int pair = g_perm[basep + gr]; ws = g_topkw[pair]; dst = g_y + (size_t)pair * DDIM; }
            }
            if (!ok) continue;
#pragma unroll
            for (int nt = 0; nt < 8; nt++) {
                int col = n0 + wc2 + nt * 8 + (lane & 3) * 2;
                float2 v;
                v.x = acc[mt][nt][rh * 2 + 0] * ws;
                v.y = acc[mt][nt][rh * 2 + 1] * ws;
                *(float2*)(dst + col) = v;
            }
        }
    }
}

// ---- combine + aux (launch #6) ----------------------------------------------
__global__ void k_combine(float* __restrict__ out, int out_size) {
    if (blockIdx.x == gridDim.x - 1) {
        __shared__ float sred[256];
        float le[EXP];
#pragma unroll
        for (int e = 0; e < EXP; e++) le[e] = 0.f;
        for (int t = threadIdx.x; t < NTOK; t += 256)
#pragma unroll
            for (int e = 0; e < EXP; e++) le[e] += g_probs[(size_t)t * EXP + e];
        float aux = 0.f;
        for (int e = 0; e < EXP; e++) {
            sred[threadIdx.x] = le[e];
            __syncthreads();
            for (int s = 128; s; s >>= 1) {
                if (threadIdx.x < s) sred[threadIdx.x] += sred[threadIdx.x + s];
                __syncthreads();
            }
            if (threadIdx.x == 0) {
                float load = sred[0] * (1.f / NTOK);
                float d = load - (1.f / EXP);
                aux += d * d;
            }
            __syncthreads();
        }
        if (threadIdx.x == 0 && out_size > NTOK * DDIM)
            out[NTOK * DDIM] = 0.001f * aux;
        return;
    }
    int i = blockIdx.x * blockDim.x + threadIdx.x;
    if (i >= NTOK * (DDIM / 4)) return;
    int t = i >> 8;
    int c = (i & 255) << 2;
    float4 y0 = *(const float4*)(g_y + (size_t)(2 * t + 0) * DDIM + c);
    float4 y1 = *(const float4*)(g_y + (size_t)(2 * t + 1) * DDIM + c);
    float4 sh = *(const float4*)(g_shf + (size_t)t * DDIM + c);
    float sg = g_sgate[t];
    float4 o;
    o.x = y0.x + y1.x + sg * sh.x;
    o.y = y0.y + y1.y + sg * sh.y;
    o.z = y0.z + y1.z + sg * sh.z;
    o.w = y0.w + y1.w + sg * sh.w;
    *(float4*)(out + (size_t)t * DDIM + c) = o;
}

// ---------------- launch -----------------------------------------------------
extern "C" void kernel_launch(void* const* d_in, const int* in_sizes, int n_in,
                              void* d_out, int out_size) {
    const float* x   = (const float*)d_in[0];   // [B,T,D]
    const float* gup = (const float*)d_in[1];   // [E,2F,D]
    const float* dwn = (const float*)d_in[2];   // [E,D,F]
    const float* rw  = (const float*)d_in[3];   // [D,E]
    const float* shg = (const float*)d_in[4];   // [D,FS]
    const float* shu = (const float*)d_in[5];   // [D,FS]
    const float* shd = (const float*)d_in[6];   // [FS,D]
    const float* sgw = (const float*)d_in[7];   // [D,1]
    float* out = (float*)d_out;

    cudaFuncSetAttribute((const void*)k_up,   cudaFuncAttributeMaxDynamicSharedMemorySize, SMBYTES);
    cudaFuncSetAttribute((const void*)k_down, cudaFuncAttributeMaxDynamicSharedMemorySize, SMBYTES);

    k_cvt_mega<<<NB_CVT, 256>>>(x, gup, dwn, shg, shu, shd);          // 1
    k_router<<<NTOK / 4, 128>>>(x, rw, sgw);                          // 2
    k_scansc<<<1, 256>>>();                                           // 3
    k_up<<<256 + EXP * 32 * 4, 512, SMBYTES>>>();                     // 4  <- profiled
    k_down<<<64 + EXP * 32 * 4, 512, SMBYTES>>>();                    // 5
    k_combine<<<(NTOK * (DDIM / 4)) / 256 + 1, 256>>>(out, out_size); // 6
}